// round 8
// baseline (speedup 1.0000x reference)
#include <cuda_runtime.h>
#include <cstdint>

// MotorLayer: out[j] = sum_i weight[j,i] * input[i, j<3 ? 0 : 1]
// R8: TMA bulk pipeline, bigger chunks. CI=2048 (stage 64KB: input 16KB +
// 6x8KB weights), STAGES=3 (192KB smem). Same in-flight depth as R7 but
// half the per-byte mbarrier wakeup/arrive cost at the consumers.

#define N_IN     8388608
#define CI       2048                   // i-values per chunk
#define NCHUNK   (N_IN / CI)            // 4096
#define GRID     148
#define CONS_T   256                    // consumer threads (warps 0-7)
#define THREADS  288                    // + producer warp 8
#define NWARPS   (THREADS / 32)         // 9
#define STAGES   3
#define IN_BYTES   (CI * 2 * 4)         // 16384
#define W_BYTES    (CI * 4)             // 8192
#define STAGE_BYTES (IN_BYTES + 6 * W_BYTES)  // 65536
#define SMEM_DYN   (STAGES * STAGE_BYTES)     // 196608

__device__ float g_partials[GRID * 6];
__device__ unsigned int g_count = 0;

// ---- minimal PTX helpers ----
__device__ __forceinline__ uint32_t smem_u32(const void* p) {
    uint32_t a;
    asm("{ .reg .u64 t; cvta.to.shared.u64 t, %1; cvt.u32.u64 %0, t; }" : "=r"(a) : "l"(p));
    return a;
}
#define MBAR_INIT(addr, cnt) \
    asm volatile("mbarrier.init.shared.b64 [%0], %1;" :: "r"(addr), "r"(cnt) : "memory")
#define MBAR_EXPECT_TX(addr, bytes) \
    asm volatile("mbarrier.arrive.expect_tx.shared.b64 _, [%0], %1;" :: "r"(addr), "r"(bytes) : "memory")
#define MBAR_ARRIVE(addr) \
    asm volatile("mbarrier.arrive.shared.b64 _, [%0];" :: "r"(addr) : "memory")
#define MBAR_WAIT(addr, parity) do {                                              \
    asm volatile(                                                                 \
        "{\n\t.reg .pred P1;\n\t"                                                 \
        "WAIT_LOOP_%=:\n\t"                                                       \
        "mbarrier.try_wait.parity.acquire.cta.shared::cta.b64 P1, [%0], %1, 0x989680;\n\t" \
        "@P1 bra.uni WAIT_DONE_%=;\n\t"                                           \
        "bra.uni WAIT_LOOP_%=;\n\t"                                               \
        "WAIT_DONE_%=:\n\t}"                                                      \
        :: "r"(addr), "r"(parity) : "memory");                                    \
} while (0)
#define BULK_G2S(dst, src, bytes, mbar)                                           \
    asm volatile("cp.async.bulk.shared::cluster.global.mbarrier::complete_tx::bytes " \
                 "[%0], [%1], %2, [%3];"                                          \
                 :: "r"(dst), "l"(src), "r"(bytes), "r"(mbar) : "memory")

__global__ __launch_bounds__(THREADS, 1)
void motor_tma(const float* __restrict__ inp,    // [8388608, 2]
               const float* __restrict__ w,      // [6, 8388608]
               float* __restrict__ out)
{
    extern __shared__ char dyn[];
    __shared__ __align__(16) uint64_t mbar[2 * STAGES];   // [full..., empty...]
    __shared__ float rsm[NWARPS][6];
    __shared__ bool is_last;

    const int tid  = threadIdx.x;
    const int warp = tid >> 5;
    const int lane = tid & 31;
    const uint32_t dyn_base  = smem_u32(dyn);
    const uint32_t mbar_base = smem_u32(mbar);

    if (tid == 0) {
        #pragma unroll
        for (int s = 0; s < STAGES; s++) {
            MBAR_INIT(mbar_base + s * 8, 1);                    // full: producer expect_tx
            MBAR_INIT(mbar_base + (STAGES + s) * 8, CONS_T);    // empty: all consumers arrive
        }
    }
    __syncthreads();

    float s0 = 0.f, s1 = 0.f, s2 = 0.f, s3 = 0.f, s4 = 0.f, s5 = 0.f;

    if (warp == 8) {
        // ---- producer warp: lane 0 issues bulk copies, ring of STAGES ----
        if (lane == 0) {
            int stage = 0, phase = 1;   // phase=1: first empty-wait passes immediately
            for (int k = blockIdx.x; k < NCHUNK; k += GRID) {
                const uint32_t emp = mbar_base + (STAGES + stage) * 8;
                const uint32_t ful = mbar_base + stage * 8;
                MBAR_WAIT(emp, phase);
                MBAR_EXPECT_TX(ful, STAGE_BYTES);
                const uint32_t sb = dyn_base + stage * STAGE_BYTES;
                BULK_G2S(sb, inp + (size_t)k * CI * 2, IN_BYTES, ful);
                #pragma unroll
                for (int r = 0; r < 6; r++)
                    BULK_G2S(sb + IN_BYTES + r * W_BYTES,
                             w + (size_t)r * N_IN + (size_t)k * CI, W_BYTES, ful);
                if (++stage == STAGES) { stage = 0; phase ^= 1; }
            }
        }
    } else {
        // ---- consumer warps 0-7 (256 threads): 2 float4 per row per chunk ----
        int stage = 0, phase = 0;
        for (int k = blockIdx.x; k < NCHUNK; k += GRID) {
            const uint32_t ful = mbar_base + stage * 8;
            const uint32_t emp = mbar_base + (STAGES + stage) * 8;
            MBAR_WAIT(ful, phase);

            const char* sb = dyn + stage * STAGE_BYTES;
            const float4* sin = (const float4*)sb;                 // 1024 float4
            const float4* sw  = (const float4*)(sb + IN_BYTES);    // 6 x 512 float4

            #pragma unroll
            for (int u = 0; u < 2; u++) {
                const int t = tid + u * CONS_T;                    // 0..511
                float4 p  = sin[2 * t + 0];
                float4 q  = sin[2 * t + 1];
                float4 w0 = sw[0 * (CI / 4) + t];
                float4 w1 = sw[1 * (CI / 4) + t];
                float4 w2 = sw[2 * (CI / 4) + t];
                float4 w3 = sw[3 * (CI / 4) + t];
                float4 w4 = sw[4 * (CI / 4) + t];
                float4 w5 = sw[5 * (CI / 4) + t];

                s0 += w0.x * p.x + w0.y * p.z + w0.z * q.x + w0.w * q.z;
                s1 += w1.x * p.x + w1.y * p.z + w1.z * q.x + w1.w * q.z;
                s2 += w2.x * p.x + w2.y * p.z + w2.z * q.x + w2.w * q.z;
                s3 += w3.x * p.y + w3.y * p.w + w3.z * q.y + w3.w * q.w;
                s4 += w4.x * p.y + w4.y * p.w + w4.z * q.y + w4.w * q.w;
                s5 += w5.x * p.y + w5.y * p.w + w5.z * q.y + w5.w * q.w;
            }

            MBAR_ARRIVE(emp);           // release: my reads done, buffer reusable
            if (++stage == STAGES) { stage = 0; phase ^= 1; }
        }

        // warp reduction (fixed pattern)
        #pragma unroll
        for (int off = 16; off > 0; off >>= 1) {
            s0 += __shfl_down_sync(0xffffffffu, s0, off);
            s1 += __shfl_down_sync(0xffffffffu, s1, off);
            s2 += __shfl_down_sync(0xffffffffu, s2, off);
            s3 += __shfl_down_sync(0xffffffffu, s3, off);
            s4 += __shfl_down_sync(0xffffffffu, s4, off);
            s5 += __shfl_down_sync(0xffffffffu, s5, off);
        }
        if (lane == 0) {
            rsm[warp][0] = s0; rsm[warp][1] = s1; rsm[warp][2] = s2;
            rsm[warp][3] = s3; rsm[warp][4] = s4; rsm[warp][5] = s5;
        }
    }
    __syncthreads();

    if (tid == 0) {
        float t0 = 0.f, t1 = 0.f, t2 = 0.f, t3 = 0.f, t4 = 0.f, t5 = 0.f;
        #pragma unroll
        for (int wr = 0; wr < 8; wr++) {
            t0 += rsm[wr][0]; t1 += rsm[wr][1]; t2 += rsm[wr][2];
            t3 += rsm[wr][3]; t4 += rsm[wr][4]; t5 += rsm[wr][5];
        }
        float* dst = &g_partials[blockIdx.x * 6];
        dst[0] = t0; dst[1] = t1; dst[2] = t2;
        dst[3] = t3; dst[4] = t4; dst[5] = t5;
        __threadfence();
        unsigned prev = atomicAdd(&g_count, 1u);
        is_last = (prev == GRID - 1);
    }
    __syncthreads();
    if (!is_last) return;

    // final block: reduce GRID x 6 partials (3.5 KB, L2-hot)
    __threadfence();
    float t0 = 0.f, t1 = 0.f, t2 = 0.f, t3 = 0.f, t4 = 0.f, t5 = 0.f;
    for (int b = tid; b < GRID; b += THREADS) {
        const float* src = &g_partials[b * 6];
        t0 += src[0]; t1 += src[1]; t2 += src[2];
        t3 += src[3]; t4 += src[4]; t5 += src[5];
    }
    #pragma unroll
    for (int off = 16; off > 0; off >>= 1) {
        t0 += __shfl_down_sync(0xffffffffu, t0, off);
        t1 += __shfl_down_sync(0xffffffffu, t1, off);
        t2 += __shfl_down_sync(0xffffffffu, t2, off);
        t3 += __shfl_down_sync(0xffffffffu, t3, off);
        t4 += __shfl_down_sync(0xffffffffu, t4, off);
        t5 += __shfl_down_sync(0xffffffffu, t5, off);
    }
    __syncthreads();
    if (lane == 0) {
        rsm[warp][0] = t0; rsm[warp][1] = t1; rsm[warp][2] = t2;
        rsm[warp][3] = t3; rsm[warp][4] = t4; rsm[warp][5] = t5;
    }
    __syncthreads();
    if (tid == 0) {
        float r0 = 0.f, r1 = 0.f, r2 = 0.f, r3 = 0.f, r4 = 0.f, r5 = 0.f;
        #pragma unroll
        for (int wr = 0; wr < NWARPS; wr++) {
            r0 += rsm[wr][0]; r1 += rsm[wr][1]; r2 += rsm[wr][2];
            r3 += rsm[wr][3]; r4 += rsm[wr][4]; r5 += rsm[wr][5];
        }
        out[0] = r0; out[1] = r1; out[2] = r2;
        out[3] = r3; out[4] = r4; out[5] = r5;
        g_count = 0;   // reset for graph replay
    }
}

extern "C" void kernel_launch(void* const* d_in, const int* in_sizes, int n_in,
                              void* d_out, int out_size) {
    const float* inp = (const float*)d_in[0];   // input  [8388608, 2] fp32
    const float* w   = (const float*)d_in[1];   // weight [6, 8388608] fp32
    float* out = (float*)d_out;

    cudaFuncSetAttribute(motor_tma, cudaFuncAttributeMaxDynamicSharedMemorySize, SMEM_DYN);
    motor_tma<<<GRID, THREADS, SMEM_DYN>>>(inp, w, out);
}

// round 9
// speedup vs baseline: 1.0280x; 1.0280x over previous
#include <cuda_runtime.h>
#include <cstdint>

// MotorLayer: out[j] = sum_i weight[j,i] * input[i, j<3 ? 0 : 1]
// R9: R7 base (CI=1024, 32KB stages) with (a) STAGES=5 (160KB smem) and
// (b) empty-mbarrier arrivals reduced 256 -> 8 (one per warp, lane 0 after
// __syncwarp) to kill the same-address arrive serialization that gated
// TMA stage reissue.

#define N_IN     8388608
#define CI       1024                   // i-values per chunk
#define NCHUNK   (N_IN / CI)            // 8192
#define GRID     148
#define CONS_T   256                    // consumer threads (warps 0-7)
#define CONS_W   8
#define THREADS  288                    // + producer warp 8
#define NWARPS   (THREADS / 32)         // 9
#define STAGES   5
#define IN_BYTES   (CI * 2 * 4)         // 8192
#define W_BYTES    (CI * 4)             // 4096
#define STAGE_BYTES (IN_BYTES + 6 * W_BYTES)  // 32768
#define SMEM_DYN   (STAGES * STAGE_BYTES)     // 163840

__device__ float g_partials[GRID * 6];
__device__ unsigned int g_count = 0;

// ---- minimal PTX helpers ----
__device__ __forceinline__ uint32_t smem_u32(const void* p) {
    uint32_t a;
    asm("{ .reg .u64 t; cvta.to.shared.u64 t, %1; cvt.u32.u64 %0, t; }" : "=r"(a) : "l"(p));
    return a;
}
#define MBAR_INIT(addr, cnt) \
    asm volatile("mbarrier.init.shared.b64 [%0], %1;" :: "r"(addr), "r"(cnt) : "memory")
#define MBAR_EXPECT_TX(addr, bytes) \
    asm volatile("mbarrier.arrive.expect_tx.shared.b64 _, [%0], %1;" :: "r"(addr), "r"(bytes) : "memory")
#define MBAR_ARRIVE(addr) \
    asm volatile("mbarrier.arrive.shared.b64 _, [%0];" :: "r"(addr) : "memory")
#define MBAR_WAIT(addr, parity) do {                                              \
    asm volatile(                                                                 \
        "{\n\t.reg .pred P1;\n\t"                                                 \
        "WAIT_LOOP_%=:\n\t"                                                       \
        "mbarrier.try_wait.parity.acquire.cta.shared::cta.b64 P1, [%0], %1, 0x989680;\n\t" \
        "@P1 bra.uni WAIT_DONE_%=;\n\t"                                           \
        "bra.uni WAIT_LOOP_%=;\n\t"                                               \
        "WAIT_DONE_%=:\n\t}"                                                      \
        :: "r"(addr), "r"(parity) : "memory");                                    \
} while (0)
#define BULK_G2S(dst, src, bytes, mbar)                                           \
    asm volatile("cp.async.bulk.shared::cluster.global.mbarrier::complete_tx::bytes " \
                 "[%0], [%1], %2, [%3];"                                          \
                 :: "r"(dst), "l"(src), "r"(bytes), "r"(mbar) : "memory")

__global__ __launch_bounds__(THREADS, 1)
void motor_tma(const float* __restrict__ inp,    // [8388608, 2]
               const float* __restrict__ w,      // [6, 8388608]
               float* __restrict__ out)
{
    extern __shared__ char dyn[];
    __shared__ __align__(16) uint64_t mbar[2 * STAGES];   // [full..., empty...]
    __shared__ float rsm[NWARPS][6];
    __shared__ bool is_last;

    const int tid  = threadIdx.x;
    const int warp = tid >> 5;
    const int lane = tid & 31;
    const uint32_t dyn_base  = smem_u32(dyn);
    const uint32_t mbar_base = smem_u32(mbar);

    if (tid == 0) {
        #pragma unroll
        for (int s = 0; s < STAGES; s++) {
            MBAR_INIT(mbar_base + s * 8, 1);                    // full: producer expect_tx
            MBAR_INIT(mbar_base + (STAGES + s) * 8, CONS_W);    // empty: 1 arrive per warp
        }
    }
    __syncthreads();

    float s0 = 0.f, s1 = 0.f, s2 = 0.f, s3 = 0.f, s4 = 0.f, s5 = 0.f;

    if (warp == 8) {
        // ---- producer warp: lane 0 issues bulk copies, ring of STAGES ----
        if (lane == 0) {
            int stage = 0, phase = 1;   // phase=1: first empty-wait passes immediately
            for (int k = blockIdx.x; k < NCHUNK; k += GRID) {
                const uint32_t emp = mbar_base + (STAGES + stage) * 8;
                const uint32_t ful = mbar_base + stage * 8;
                MBAR_WAIT(emp, phase);
                MBAR_EXPECT_TX(ful, STAGE_BYTES);
                const uint32_t sb = dyn_base + stage * STAGE_BYTES;
                BULK_G2S(sb, inp + (size_t)k * CI * 2, IN_BYTES, ful);
                #pragma unroll
                for (int r = 0; r < 6; r++)
                    BULK_G2S(sb + IN_BYTES + r * W_BYTES,
                             w + (size_t)r * N_IN + (size_t)k * CI, W_BYTES, ful);
                if (++stage == STAGES) { stage = 0; phase ^= 1; }
            }
        }
    } else {
        // ---- consumer warps 0-7 (256 threads): one float4-group each per chunk ----
        int stage = 0, phase = 0;
        for (int k = blockIdx.x; k < NCHUNK; k += GRID) {
            const uint32_t ful = mbar_base + stage * 8;
            const uint32_t emp = mbar_base + (STAGES + stage) * 8;
            MBAR_WAIT(ful, phase);

            const char* sb = dyn + stage * STAGE_BYTES;
            const float4* sin = (const float4*)sb;                 // 512 float4
            const float4* sw  = (const float4*)(sb + IN_BYTES);    // 6 x 256 float4

            float4 p  = sin[2 * tid + 0];
            float4 q  = sin[2 * tid + 1];
            float4 w0 = sw[0 * (CI / 4) + tid];
            float4 w1 = sw[1 * (CI / 4) + tid];
            float4 w2 = sw[2 * (CI / 4) + tid];
            float4 w3 = sw[3 * (CI / 4) + tid];
            float4 w4 = sw[4 * (CI / 4) + tid];
            float4 w5 = sw[5 * (CI / 4) + tid];

            s0 += w0.x * p.x + w0.y * p.z + w0.z * q.x + w0.w * q.z;
            s1 += w1.x * p.x + w1.y * p.z + w1.z * q.x + w1.w * q.z;
            s2 += w2.x * p.x + w2.y * p.z + w2.z * q.x + w2.w * q.z;
            s3 += w3.x * p.y + w3.y * p.w + w3.z * q.y + w3.w * q.w;
            s4 += w4.x * p.y + w4.y * p.w + w4.z * q.y + w4.w * q.w;
            s5 += w5.x * p.y + w5.y * p.w + w5.z * q.y + w5.w * q.w;

            // All lanes' smem values are consumed (FFMA register deps force LDS
            // completion); sync the warp, then one arrive for the whole warp.
            __syncwarp();
            if (lane == 0) MBAR_ARRIVE(emp);
            if (++stage == STAGES) { stage = 0; phase ^= 1; }
        }

        // warp reduction (fixed pattern)
        #pragma unroll
        for (int off = 16; off > 0; off >>= 1) {
            s0 += __shfl_down_sync(0xffffffffu, s0, off);
            s1 += __shfl_down_sync(0xffffffffu, s1, off);
            s2 += __shfl_down_sync(0xffffffffu, s2, off);
            s3 += __shfl_down_sync(0xffffffffu, s3, off);
            s4 += __shfl_down_sync(0xffffffffu, s4, off);
            s5 += __shfl_down_sync(0xffffffffu, s5, off);
        }
        if (lane == 0) {
            rsm[warp][0] = s0; rsm[warp][1] = s1; rsm[warp][2] = s2;
            rsm[warp][3] = s3; rsm[warp][4] = s4; rsm[warp][5] = s5;
        }
    }
    __syncthreads();

    if (tid == 0) {
        float t0 = 0.f, t1 = 0.f, t2 = 0.f, t3 = 0.f, t4 = 0.f, t5 = 0.f;
        #pragma unroll
        for (int wr = 0; wr < CONS_W; wr++) {
            t0 += rsm[wr][0]; t1 += rsm[wr][1]; t2 += rsm[wr][2];
            t3 += rsm[wr][3]; t4 += rsm[wr][4]; t5 += rsm[wr][5];
        }
        float* dst = &g_partials[blockIdx.x * 6];
        dst[0] = t0; dst[1] = t1; dst[2] = t2;
        dst[3] = t3; dst[4] = t4; dst[5] = t5;
        __threadfence();
        unsigned prev = atomicAdd(&g_count, 1u);
        is_last = (prev == GRID - 1);
    }
    __syncthreads();
    if (!is_last) return;

    // final block: reduce GRID x 6 partials (3.5 KB, L2-hot)
    __threadfence();
    float t0 = 0.f, t1 = 0.f, t2 = 0.f, t3 = 0.f, t4 = 0.f, t5 = 0.f;
    for (int b = tid; b < GRID; b += THREADS) {
        const float* src = &g_partials[b * 6];
        t0 += src[0]; t1 += src[1]; t2 += src[2];
        t3 += src[3]; t4 += src[4]; t5 += src[5];
    }
    #pragma unroll
    for (int off = 16; off > 0; off >>= 1) {
        t0 += __shfl_down_sync(0xffffffffu, t0, off);
        t1 += __shfl_down_sync(0xffffffffu, t1, off);
        t2 += __shfl_down_sync(0xffffffffu, t2, off);
        t3 += __shfl_down_sync(0xffffffffu, t3, off);
        t4 += __shfl_down_sync(0xffffffffu, t4, off);
        t5 += __shfl_down_sync(0xffffffffu, t5, off);
    }
    __syncthreads();
    if (lane == 0) {
        rsm[warp][0] = t0; rsm[warp][1] = t1; rsm[warp][2] = t2;
        rsm[warp][3] = t3; rsm[warp][4] = t4; rsm[warp][5] = t5;
    }
    __syncthreads();
    if (tid == 0) {
        float r0 = 0.f, r1 = 0.f, r2 = 0.f, r3 = 0.f, r4 = 0.f, r5 = 0.f;
        #pragma unroll
        for (int wr = 0; wr < NWARPS; wr++) {
            r0 += rsm[wr][0]; r1 += rsm[wr][1]; r2 += rsm[wr][2];
            r3 += rsm[wr][3]; r4 += rsm[wr][4]; r5 += rsm[wr][5];
        }
        out[0] = r0; out[1] = r1; out[2] = r2;
        out[3] = r3; out[4] = r4; out[5] = r5;
        g_count = 0;   // reset for graph replay
    }
}

extern "C" void kernel_launch(void* const* d_in, const int* in_sizes, int n_in,
                              void* d_out, int out_size) {
    const float* inp = (const float*)d_in[0];   // input  [8388608, 2] fp32
    const float* w   = (const float*)d_in[1];   // weight [6, 8388608] fp32
    float* out = (float*)d_out;

    cudaFuncSetAttribute(motor_tma, cudaFuncAttributeMaxDynamicSharedMemorySize, SMEM_DYN);
    motor_tma<<<GRID, THREADS, SMEM_DYN>>>(inp, w, out);
}